// round 11
// baseline (speedup 1.0000x reference)
#include <cuda_runtime.h>
#include <string.h>

#define BATCH 128
#define TLEN  8192
#define HDIM  96
#define NTHR  768   // 24 gate warps; no output warp (y done in post-pass)

// 402MB device scratch for the h history (documented workaround for no-alloc rule)
__device__ float g_hist[(size_t)BATCH * HDIM * TLEN];

// Packed fp32x2 FMA (Blackwell): rt=2/SMSP, 2 MACs per issue.
#define FMA2(d, a, b, c) \
    asm("fma.rn.f32x2 %0, %1, %2, %3;" : "=l"(d) : "l"(a), "l"(b), "l"(c))
#define ADD2(d, a, b) \
    asm("add.rn.f32x2 %0, %1, %2;" : "=l"(d) : "l"(a), "l"(b))
#define UNPACK2(lo, hi, v) \
    asm("mov.b64 {%0, %1}, %2;" : "=f"(lo), "=f"(hi) : "l"(v))

__device__ __forceinline__ float ex2_fast(float x) {
    float y; asm("ex2.approx.f32 %0, %1;" : "=f"(y) : "f"(x)); return y;
}
__device__ __forceinline__ float rcp_fast(float x) {
    float y; asm("rcp.approx.f32 %0, %1;" : "=f"(y) : "f"(x)); return y;
}

#define LOG2E 1.4426950408889634f

// One LSTM step. Lane layout: 8 lanes per unit; sub = lane&7 encodes
// (gate g = sub&3, half hh = sub>>2). Each lane: gate g's row over h-half hh.
// Reduction is a single shfl_xor(4) (partner = same gate, other half).
__device__ __forceinline__ void lstm_step(
    const float* __restrict__ hin,    // h_s[phase] + 48*hh
    float* __restrict__ hout,         // h_s[phase^1]
    float* __restrict__ hist, int t,  // g_hist row for unit u
    float xt,
    const ulonglong2 (&wreg)[12], float wi, float bias, float mq,
    int base, int u, float& c)
{
    const ulonglong2* hq = (const ulonglong2*)hin;
    float pre = fmaf(xt, wi, bias);

    unsigned long long a0 = 0ull, a1 = 0ull;
    #pragma unroll
    for (int j = 0; j < 12; j += 2) {
        ulonglong2 hv0 = hq[j];
        FMA2(a0, wreg[j].x,     hv0.x, a0);
        FMA2(a1, wreg[j].y,     hv0.y, a1);
        ulonglong2 hv1 = hq[j + 1];
        FMA2(a0, wreg[j + 1].x, hv1.x, a0);
        FMA2(a1, wreg[j + 1].y, hv1.y, a1);
    }
    ADD2(a0, a0, a1);
    float lo, hi;
    UNPACK2(lo, hi, a0);
    float partial = lo + hi;

    // single-stage reduction: add partner half's partial
    float z = partial + __shfl_xor_sync(0xffffffffu, partial, 4) + pre;

    // branchless activation in log2 domain: 1 - mq/(2^z + 1)
    float e   = ex2_fast(z);
    float r   = rcp_fast(e + 1.0f);
    float act = fmaf(-mq, r, 1.0f);

    // gather i,f,g,o of this unit (lanes base+0..3; parallel shfls)
    float iv = __shfl_sync(0xffffffffu, act, base);
    float fv = __shfl_sync(0xffffffffu, act, base + 1);
    float gv = __shfl_sync(0xffffffffu, act, base + 2);
    float ov = __shfl_sync(0xffffffffu, act, base + 3);

    // redundant branchless update on all 8 lanes (identical values)
    c = fmaf(fv, c, iv * gv);
    float e2 = ex2_fast(c * (2.0f * LOG2E));
    float hc = ov * fmaf(-2.0f, rcp_fast(e2 + 1.0f), 1.0f);
    hout[u] = hc;     // same-address stores collapse (R6-verified pattern)
    hist[t] = hc;     // h history for the y post-pass; off the critical chain
}

__global__ void __launch_bounds__(NTHR, 1)
lstm_persistent_kernel(const float* __restrict__ x,
                       const float* __restrict__ w_ih,
                       const float* __restrict__ w_hh,
                       const float* __restrict__ b_ih,
                       const float* __restrict__ b_hh,
                       const float* __restrict__ w_out,
                       const float* __restrict__ b_out,
                       float* __restrict__ out)
{
    __shared__ __align__(16) float x_s[TLEN];      // 32 KB: whole input row
    __shared__ __align__(16) float h_s[2][HDIM];   // ping-pong hidden state
    __shared__ float wout_s[HDIM];

    const int tid  = threadIdx.x;
    const int b    = blockIdx.x;
    const int wid  = tid >> 5;
    const int lane = tid & 31;

    {   // stage whole x row, coalesced float4
        const float4* xg = (const float4*)(x + (size_t)b * TLEN);
        float4* xs = (float4*)x_s;
        for (int i = tid; i < TLEN / 4; i += NTHR) xs[i] = xg[i];
    }
    if (tid < HDIM) {
        h_s[0][tid] = 0.0f;
        h_s[1][tid] = 0.0f;
        wout_s[tid] = w_out[tid];
    }

    const int u   = 4 * wid + (lane >> 3);   // hidden unit 0..95
    const int sub = lane & 7;
    const int g   = sub & 3;                 // gate id 0=i 1=f 2=g 3=o
    const int hh  = sub >> 2;                // h-half 0/1

    const float sg = (g == 2) ? 2.0f * LOG2E : LOG2E;
    const float mq = (g == 2) ? 2.0f : 1.0f;
    const int row  = g * HDIM + u;

    // gate g's W_hh row over columns [48*hh, 48*hh+48), prescaled (log2 domain)
    ulonglong2 wreg[12];
    {
        const float4* wr = (const float4*)(w_hh + (size_t)row * HDIM + 48 * hh);
        #pragma unroll
        for (int j = 0; j < 12; j++) {
            float4 tv = wr[j];
            tv.x *= sg; tv.y *= sg; tv.z *= sg; tv.w *= sg;
            ulonglong2 pk;
            memcpy(&pk, &tv, 16);
            wreg[j] = pk;
        }
    }
    const float wi   = w_ih[row] * sg;
    const float bias = (b_ih[row] + b_hh[row]) * sg;
    const int   base = lane & ~7;

    float* hist = g_hist + ((size_t)b * HDIM + u) * TLEN;
    const float* hin0 = h_s[0] + 48 * hh;
    const float* hin1 = h_s[1] + 48 * hh;

    __syncthreads();   // x_s, h init, weights ready

    float c = 0.0f;
    #pragma unroll 1
    for (int t = 0; t < TLEN; t += 2) {
        lstm_step(hin0, h_s[1], hist, t,     x_s[t],
                  wreg, wi, bias, mq, base, u, c);
        __syncthreads();
        lstm_step(hin1, h_s[0], hist, t + 1, x_s[t + 1],
                  wreg, wi, bias, mq, base, u, c);
        __syncthreads();
    }

    // ---------------- y post-pass: out[b][t] = <w_out, h(t)> + b_out ----------
    // g_hist layout [b][u][t]: consecutive lanes read consecutive t -> coalesced.
    const float bo = b_out[0];
    const float* hb = g_hist + (size_t)b * HDIM * TLEN;
    float* outrow = out + (size_t)b * TLEN;
    #pragma unroll 1
    for (int t = tid; t < TLEN; t += NTHR) {
        float y = bo;
        #pragma unroll
        for (int uu = 0; uu < HDIM; uu++)
            y = fmaf(wout_s[uu], hb[(size_t)uu * TLEN + t], y);
        outrow[t] = y;
    }
}

extern "C" void kernel_launch(void* const* d_in, const int* in_sizes, int n_in,
                              void* d_out, int out_size)
{
    const float* x     = (const float*)d_in[0];
    const float* w_ih  = (const float*)d_in[1];
    const float* w_hh  = (const float*)d_in[2];
    const float* b_ih  = (const float*)d_in[3];
    const float* b_hh  = (const float*)d_in[4];
    const float* w_out = (const float*)d_in[5];
    const float* b_out = (const float*)d_in[6];
    float* out = (float*)d_out;

    lstm_persistent_kernel<<<BATCH, NTHR>>>(x, w_ih, w_hh, b_ih, b_hh,
                                            w_out, b_out, out);
}

// round 12
// speedup vs baseline: 1.2794x; 1.2794x over previous
#include <cuda_runtime.h>
#include <string.h>

#define BATCH 128
#define TLEN  8192
#define HDIM  96
#define NTHR  416   // 12 gate warps + 1 output warp

// Packed fp32x2 FMA (Blackwell): rt=2/SMSP, 2 MACs per issue.
#define FMA2(d, a, b, c) \
    asm("fma.rn.f32x2 %0, %1, %2, %3;" : "=l"(d) : "l"(a), "l"(b), "l"(c))
#define ADD2(d, a, b) \
    asm("add.rn.f32x2 %0, %1, %2;" : "=l"(d) : "l"(a), "l"(b))
#define UNPACK2(lo, hi, v) \
    asm("mov.b64 {%0, %1}, %2;" : "=f"(lo), "=f"(hi) : "l"(v))

__device__ __forceinline__ float ex2_fast(float x) {
    float y; asm("ex2.approx.f32 %0, %1;" : "=f"(y) : "f"(x)); return y;
}
__device__ __forceinline__ float rcp_fast(float x) {
    float y; asm("rcp.approx.f32 %0, %1;" : "=f"(y) : "f"(x)); return y;
}
__device__ __forceinline__ void cta_bar() {
    asm volatile("bar.sync 0;" ::: "memory");
}

#define LOG2E 1.4426950408889634f

// One LSTM step. XOR-permuted slots: lane q holds, in slot s, gate (q^s)'s
// partial over h-quarter q. Select-free butterfly:
//   s1a = pg0 + shfl_xor(pg1,1); s1b = pg2 + shfl_xor(pg3,1);
//   z   = (s1a + pre) + shfl_xor(s1b,2)   -> lane q owns gate q's full sum.
// Cell state kept in scaled domain C = 2*log2e*c (gate-2 act pre-scaled),
// so tanh(c) = 1 - 2*rcp(ex2(C)+1) with no chain-side multiply.
__device__ __forceinline__ void lstm_step(
    const float* __restrict__ hin, float* __restrict__ hout, float pre,
    const ulonglong2 (&wreg)[4][6], float Aq, float Bq,
    int base, int u, float& C)
{
    const ulonglong2* hq = (const ulonglong2*)hin;   // hin already offset by 24q
    ulonglong2 h0 = hq[0], h1 = hq[1], h2v = hq[2];
    ulonglong2 h3 = hq[3], h4 = hq[4], h5 = hq[5];

    unsigned long long acc[4][2];
    #pragma unroll
    for (int s = 0; s < 4; s++) { acc[s][0] = 0ull; acc[s][1] = 0ull; }
    #pragma unroll
    for (int s = 0; s < 4; s++) {
        FMA2(acc[s][0], wreg[s][0].x, h0.x, acc[s][0]);
        FMA2(acc[s][1], wreg[s][0].y, h0.y, acc[s][1]);
        FMA2(acc[s][0], wreg[s][1].x, h1.x, acc[s][0]);
        FMA2(acc[s][1], wreg[s][1].y, h1.y, acc[s][1]);
        FMA2(acc[s][0], wreg[s][2].x, h2v.x, acc[s][0]);
        FMA2(acc[s][1], wreg[s][2].y, h2v.y, acc[s][1]);
        FMA2(acc[s][0], wreg[s][3].x, h3.x, acc[s][0]);
        FMA2(acc[s][1], wreg[s][3].y, h3.y, acc[s][1]);
        FMA2(acc[s][0], wreg[s][4].x, h4.x, acc[s][0]);
        FMA2(acc[s][1], wreg[s][4].y, h4.y, acc[s][1]);
        FMA2(acc[s][0], wreg[s][5].x, h5.x, acc[s][0]);
        FMA2(acc[s][1], wreg[s][5].y, h5.y, acc[s][1]);
    }
    float pg[4];
    #pragma unroll
    for (int s = 0; s < 4; s++) {
        unsigned long long v;
        ADD2(v, acc[s][0], acc[s][1]);
        float lo, hi;
        UNPACK2(lo, hi, v);
        pg[s] = lo + hi;
    }

    // select-free butterfly
    float s1a = pg[0] + __shfl_xor_sync(0xffffffffu, pg[1], 1);
    float s1b = pg[2] + __shfl_xor_sync(0xffffffffu, pg[3], 1);
    float z   = (s1a + pre) + __shfl_xor_sync(0xffffffffu, s1b, 2);

    // activation: sigmoid lanes -> 1 - r ; gate-2 lane -> 2log2e*(1 - 2r)
    float e   = ex2_fast(z);
    float r   = rcp_fast(e + 1.0f);
    float act = fmaf(Aq, r, Bq);

    // gather i, f, g, o of this unit (4 parallel shfls; g pre-scaled by 2log2e)
    float iv = __shfl_sync(0xffffffffu, act, base);
    float fv = __shfl_sync(0xffffffffu, act, base + 1);
    float gv = __shfl_sync(0xffffffffu, act, base + 2);
    float ov = __shfl_sync(0xffffffffu, act, base + 3);

    // redundant branchless update; C = 2log2e*c recurrence
    float m2o = -2.0f * ov;                 // off the critical chain
    C = fmaf(fv, C, iv * gv);
    float e2 = ex2_fast(C);
    float hc = fmaf(m2o, rcp_fast(e2 + 1.0f), ov);
    hout[u] = hc;   // 4 sublanes store identical value (benign)
}

__global__ void __launch_bounds__(NTHR, 1)
lstm_persistent_kernel(const float* __restrict__ x,
                       const float* __restrict__ w_ih,
                       const float* __restrict__ w_hh,
                       const float* __restrict__ b_ih,
                       const float* __restrict__ b_hh,
                       const float* __restrict__ w_out,
                       const float* __restrict__ b_out,
                       float* __restrict__ out)
{
    __shared__ __align__(16) float x_s[TLEN];      // 32 KB: whole input row
    __shared__ __align__(16) float h_s[2][HDIM];   // ping-pong hidden state

    const int tid  = threadIdx.x;
    const int b    = blockIdx.x;
    const int wid  = tid >> 5;
    const int lane = tid & 31;

    {   // stage whole x row, coalesced float4
        const float4* xg = (const float4*)(x + (size_t)b * TLEN);
        float4* xs = (float4*)x_s;
        for (int i = tid; i < TLEN / 4; i += NTHR) xs[i] = xg[i];
    }
    if (tid < HDIM) { h_s[0][tid] = 0.0f; h_s[1][tid] = 0.0f; }

    const bool is_gate = (wid < 12);
    const int u = 8 * wid + (lane >> 2);   // hidden unit 0..95
    const int q = lane & 3;                // h-quarter; also final gate id

    // XOR-permuted weight slots: slot s = gate (q^s), unit u, cols [24q,24q+24),
    // prescaled into log2 domain per that gate.
    ulonglong2 wreg[4][6];
    float wi = 0.0f, bias = 0.0f;
    if (is_gate) {
        #pragma unroll
        for (int s = 0; s < 4; s++) {
            const int g = q ^ s;
            const float sg = (g == 2) ? 2.0f * LOG2E : LOG2E;
            const float4* wr = (const float4*)(w_hh + (size_t)(g * HDIM + u) * HDIM + 24 * q);
            #pragma unroll
            for (int j = 0; j < 6; j++) {
                float4 t = wr[j];
                t.x *= sg; t.y *= sg; t.z *= sg; t.w *= sg;
                ulonglong2 pk;
                memcpy(&pk, &t, 16);
                wreg[s][j] = pk;
            }
        }
        const float sq = (q == 2) ? 2.0f * LOG2E : LOG2E;
        const int row = q * HDIM + u;
        wi   = w_ih[row] * sq;
        bias = (b_ih[row] + b_hh[row]) * sq;
    }
    // activation constants: sigmoid lanes act = 1 - r; gate-2 act = 2log2e*(1-2r)
    const float Aq = (q == 2) ? -4.0f * LOG2E : -1.0f;
    const float Bq = (q == 2) ?  2.0f * LOG2E :  1.0f;
    const int  base = lane & ~3;

    float* outrow = out + (size_t)b * TLEN;

    __syncthreads();   // x_s, h init, weights ready (convergent)

    if (is_gate) {
        // ------- gate warps: uniform loop, unroll 2 (R6-proven) ---------------
        const float* hin0 = h_s[0] + 24 * q;
        const float* hin1 = h_s[1] + 24 * q;
        float C = 0.0f;
        #pragma unroll 1
        for (int t = 0; t < TLEN; t += 2) {
            float2 xx = *(const float2*)(x_s + t);      // one LDS.64 per pair
            float pre0 = fmaf(xx.x, wi, bias);
            float pre1 = fmaf(xx.y, wi, bias);
            lstm_step(hin0, h_s[1], pre0, wreg, Aq, Bq, base, u, C);
            cta_bar();
            lstm_step(hin1, h_s[0], pre1, wreg, Aq, Bq, base, u, C);
            cta_bar();
        }
    } else {
        // ------- output warp: its own uniform loop ----------------------------
        float wo0 = w_out[lane];
        float wo1 = w_out[lane + 32];
        float wo2 = w_out[lane + 64];
        float bo  = b_out[0];

        cta_bar();   // t = 0: nothing to emit yet
        #pragma unroll 1
        for (int t = 1; t < TLEN; t++) {
            const float* hprev = h_s[t & 1];   // h(t-1)
            float part = hprev[lane] * wo0 + hprev[lane + 32] * wo1
                       + hprev[lane + 64] * wo2;
            part += __shfl_xor_sync(0xffffffffu, part, 16);
            part += __shfl_xor_sync(0xffffffffu, part, 8);
            part += __shfl_xor_sync(0xffffffffu, part, 4);
            part += __shfl_xor_sync(0xffffffffu, part, 2);
            part += __shfl_xor_sync(0xffffffffu, part, 1);
            if (lane == 0) outrow[t - 1] = part + bo;
            cta_bar();
        }
        // final y(T-1): h(T-1) lives in h_s[0] (TLEN even)
        const float* hlast = h_s[0];
        float part = hlast[lane] * wo0 + hlast[lane + 32] * wo1
                   + hlast[lane + 64] * wo2;
        part += __shfl_xor_sync(0xffffffffu, part, 16);
        part += __shfl_xor_sync(0xffffffffu, part, 8);
        part += __shfl_xor_sync(0xffffffffu, part, 4);
        part += __shfl_xor_sync(0xffffffffu, part, 2);
        part += __shfl_xor_sync(0xffffffffu, part, 1);
        if (lane == 0) outrow[TLEN - 1] = part + bo;
    }
}

extern "C" void kernel_launch(void* const* d_in, const int* in_sizes, int n_in,
                              void* d_out, int out_size)
{
    const float* x     = (const float*)d_in[0];
    const float* w_ih  = (const float*)d_in[1];
    const float* w_hh  = (const float*)d_in[2];
    const float* b_ih  = (const float*)d_in[3];
    const float* b_hh  = (const float*)d_in[4];
    const float* w_out = (const float*)d_in[5];
    const float* b_out = (const float*)d_in[6];
    float* out = (float*)d_out;

    lstm_persistent_kernel<<<BATCH, NTHR>>>(x, w_ih, w_hh, b_ih, b_hh,
                                            w_out, b_out, out);
}